// round 8
// baseline (speedup 1.0000x reference)
#include <cuda_runtime.h>
#include <math.h>

#define NL 4
#define H  1024
#define E  2048
#define G3 3072
#define OUTN 50257
#define GI_ROWS (2 * G3)        // 6144 rows per layer (W_ih)
#define GH_UNITS (NL * 2 * G3)  // 24576 rows total (W_hh, all layers)

// Persistent scratch (__device__ globals; no allocation allowed).
__device__ float g_x[E];            // current layer input (E = 2H)
__device__ float g_gi[GI_ROWS];     // W_ih @ x + b_ih  (current layer)
__device__ float g_ghA[GH_UNITS];   // W_hh @ h + b_hh  (ALL layers)

__device__ __forceinline__ float sigmoidf(float x) {
    return 1.0f / (1.0f + expf(-x));
}

// ---------------------------------------------------------------------------
// gi core: block = 128 thr (4 warps) handles 2 rows of W_ih[l].
//   warps 0,1 -> row r0 (halves 0,1);  warps 2,3 -> row r0+1.
//   8 independent float4 loads per lane; x staged in shared by caller.
//   grid = 3072 blocks.
// ---------------------------------------------------------------------------
__device__ __forceinline__ void gi_core(
    const float* __restrict__ wih, const float* __restrict__ bih,
    const float* __restrict__ sx, int l) {

    __shared__ float sp[4];
    int tid  = threadIdx.x;
    int warp = tid >> 5, lane = tid & 31;

    int r0   = blockIdx.x * 2;
    int row  = r0 + (warp >> 1);
    int half = warp & 1;
    int d = (row >= G3) ? 1 : 0;        // both rows same d (G3 even, r0 even)
    int j = row - d * G3;

    const float4* wi = (const float4*)(wih + ((size_t)(l * 2 + d) * G3 + j) * E)
                       + half * 256;
    const float4* xv = (const float4*)sx + half * 256;

    float s = 0.f;
    #pragma unroll
    for (int k = 0; k < 8; k++) {
        float4 w = wi[lane + k * 32];
        float4 x = xv[lane + k * 32];
        s += w.x * x.x + w.y * x.y + w.z * x.z + w.w * x.w;
    }
    #pragma unroll
    for (int o = 16; o; o >>= 1) s += __shfl_xor_sync(0xffffffffu, s, o);

    if (lane == 0) sp[warp] = s;
    __syncthreads();

    if (tid < 2) {
        int rr = r0 + tid;
        int dd = (rr >= G3) ? 1 : 0;
        int jj = rr - dd * G3;
        g_gi[rr] = sp[tid * 2] + sp[tid * 2 + 1]
                 + bih[(size_t)(l * 2 + dd) * G3 + jj];
    }
}

// ---------------------------------------------------------------------------
// gi0: layer-0 W_ih GEMV, x staged directly from the embedding table.
// ---------------------------------------------------------------------------
__global__ void __launch_bounds__(128) gi0_kernel(
    const float* __restrict__ wih, const float* __restrict__ bih,
    const float* __restrict__ table, const int* __restrict__ feat) {

    __shared__ __align__(16) float sx[E];
    int tid = threadIdx.x;
    size_t tb = (size_t)feat[0] * E;
    for (int i = tid; i < E; i += 128) sx[i] = table[tb + i];
    __syncthreads();

    gi_core(wih, bih, sx, 0);
}

// ---------------------------------------------------------------------------
// gi layer l (1..3): x staged from g_x.
// ---------------------------------------------------------------------------
__global__ void __launch_bounds__(128) gi_kernel(
    const float* __restrict__ wih, const float* __restrict__ bih, int l) {

    __shared__ __align__(16) float sx[E];
    int tid = threadIdx.x;
    for (int i = tid; i < E; i += 128) sx[i] = g_x[i];
    __syncthreads();

    gi_core(wih, bih, sx, l);
}

// ---------------------------------------------------------------------------
// gh_all: W_hh GEMVs for ALL layers (independent of the layer chain; every
// layer reads the INPUT hidden).  Warp-per-row, 4 rows/block, 128 thr.
//   grid = 6144 blocks.  Homogeneous — no divergence.
// ---------------------------------------------------------------------------
__global__ void __launch_bounds__(128) gh_kernel(
    const float* __restrict__ whh, const float* __restrict__ bhh,
    const float* __restrict__ hidden) {

    __shared__ __align__(16) float sh[H];
    int tid  = threadIdx.x;
    int warp = tid >> 5, lane = tid & 31;

    int u0  = blockIdx.x * 4;           // 4 consecutive rows, same (layer,dir)
    int la  = u0 / GI_ROWS;
    int rem = u0 - la * GI_ROWS;
    int d   = (rem >= G3) ? 1 : 0;

    const float* hp = hidden + (size_t)(2 * la + d) * H;
    for (int i = tid; i < H; i += 128) sh[i] = hp[i];
    __syncthreads();

    int u = u0 + warp;
    int j = rem - d * G3 + warp;
    const float4* wh = (const float4*)(whh + ((size_t)(la * 2 + d) * G3 + j) * H);
    const float4* hv = (const float4*)sh;

    float s = 0.f;
    #pragma unroll
    for (int k = 0; k < 8; k++) {
        float4 w = wh[lane + k * 32];
        float4 h = hv[lane + k * 32];
        s += w.x * h.x + w.y * h.y + w.z * h.z + w.w * h.w;
    }
    #pragma unroll
    for (int o = 16; o; o >>= 1) s += __shfl_xor_sync(0xffffffffu, s, o);

    if (lane == 0)
        g_ghA[u] = s + bhh[(size_t)(la * 2 + d) * G3 + j];
}

// ---------------------------------------------------------------------------
// Combine: GRU nonlinearity for layer l.  16 blocks x 128 (one elem/thread,
// spread across SMs to cut the measured 5.3us latency).
// ---------------------------------------------------------------------------
__global__ void __launch_bounds__(128) combine_kernel(
    const float* __restrict__ hidden, float* __restrict__ out, int l) {

    int idx = blockIdx.x * 128 + threadIdx.x;    // 0 .. 2047
    int d = (idx >= H) ? 1 : 0;
    int j = idx - d * H;
    int base = d * G3;
    int gb = l * GI_ROWS + base;

    float ir  = g_gi[base + j],          hr = g_ghA[gb + j];
    float iz  = g_gi[base + H + j],      hz = g_ghA[gb + H + j];
    float in_ = g_gi[base + 2 * H + j],  hn = g_ghA[gb + 2 * H + j];

    float r = sigmoidf(ir + hr);
    float z = sigmoidf(iz + hz);
    float n = tanhf(in_ + r * hn);
    float hold = hidden[(size_t)(2 * l + d) * H + j];
    float hnew = (1.0f - z) * n + z * hold;

    g_x[idx] = hnew;                                  // next layer input
    out[OUTN + (size_t)(2 * l + d) * H + j] = hnew;   // new_hidden output
}

// ---------------------------------------------------------------------------
// FC: warp-per-row, 4 rows/block, 128 threads (proven ~93% DRAM).
// ---------------------------------------------------------------------------
__global__ void __launch_bounds__(128) fc_kernel(
    const float* __restrict__ fcw, const float* __restrict__ fcb,
    float* __restrict__ out) {

    __shared__ __align__(16) float sx[E];
    int tid = threadIdx.x;
    for (int i = tid; i < E; i += 128) sx[i] = g_x[i];
    __syncthreads();

    int warp = tid >> 5, lane = tid & 31;
    int r = blockIdx.x * 4 + warp;
    if (r >= OUTN) return;

    const float4* wr = (const float4*)(fcw + (size_t)r * E);
    const float4* xv = (const float4*)sx;

    float sum = 0.f;
    #pragma unroll
    for (int k = 0; k < 16; k++) {
        float4 w = wr[lane + k * 32];
        float4 x = xv[lane + k * 32];
        sum += w.x * x.x + w.y * x.y + w.z * x.z + w.w * x.w;
    }
    #pragma unroll
    for (int o = 16; o; o >>= 1) sum += __shfl_xor_sync(0xffffffffu, sum, o);

    if (lane == 0) out[r] = sum + fcb[r];
}

// ---------------------------------------------------------------------------
// 10 launches: gi0, gh_all, combine0, [gi(l), combine(l)] x3, fc.
// Graph-capturable, allocation-free, no atomics/fences.
// ---------------------------------------------------------------------------
extern "C" void kernel_launch(void* const* d_in, const int* in_sizes, int n_in,
                              void* d_out, int out_size) {
    const int*   feat   = (const int*)  d_in[0];
    const float* hidden = (const float*)d_in[1];
    const float* table  = (const float*)d_in[2];
    const float* wih    = (const float*)d_in[3];
    const float* whh    = (const float*)d_in[4];
    const float* bih    = (const float*)d_in[5];
    const float* bhh    = (const float*)d_in[6];
    const float* fcw    = (const float*)d_in[7];
    const float* fcb    = (const float*)d_in[8];
    float* out = (float*)d_out;

    gi0_kernel<<<GI_ROWS / 2, 128>>>(wih, bih, table, feat);
    gh_kernel<<<GH_UNITS / 4, 128>>>(whh, bhh, hidden);
    combine_kernel<<<16, 128>>>(hidden, out, 0);
    for (int l = 1; l < NL; l++) {
        gi_kernel<<<GI_ROWS / 2, 128>>>(wih, bih, l);
        combine_kernel<<<16, 128>>>(hidden, out, l);
    }
    fc_kernel<<<(OUTN + 3) / 4, 128>>>(fcw, fcb, out);
}

// round 9
// speedup vs baseline: 1.2376x; 1.2376x over previous
#include <cuda_runtime.h>
#include <math.h>

#define NL 4
#define H  1024
#define E  2048
#define G3 3072
#define OUTN 50257

// Persistent scratch (__device__ globals; no allocation allowed).
__device__ float g_x[E];          // current layer input (E = 2H)
__device__ float g_gi[2 * G3];    // W_ih @ x + b_ih  (current layer)
__device__ float g_gh[2 * G3];    // W_hh @ h + b_hh  (current layer)

__device__ __forceinline__ float sigmoidf(float x) {
    return 1.0f / (1.0f + expf(-x));
}

// ---------------------------------------------------------------------------
// Gates (R1-proven shape): one 256-thread block per output row (6144 rows).
//   si = w_ih[row,:] . x   (2 float4/thread from W, x direct from global/L2)
//   sh = w_hh[row,:] . h   (1 float4/thread)
// For l == 0, x comes straight from the embedding table (fused embed lookup).
// ---------------------------------------------------------------------------
__global__ void __launch_bounds__(256) gates_kernel(
    const float* __restrict__ wih, const float* __restrict__ whh,
    const float* __restrict__ bih, const float* __restrict__ bhh,
    const float* __restrict__ hidden, const float* __restrict__ table,
    const int* __restrict__ feat, int l) {

    int row = blockIdx.x;            // 0 .. 6143
    int d = (row >= G3) ? 1 : 0;
    int j = row - d * G3;

    const float4* wi = (const float4*)(wih + ((size_t)(l * 2 + d) * G3 + j) * E);
    const float4* wh = (const float4*)(whh + ((size_t)(l * 2 + d) * G3 + j) * H);
    const float4* xv = (l == 0)
        ? (const float4*)(table + (size_t)feat[0] * E)
        : (const float4*)g_x;
    const float4* hv = (const float4*)(hidden + (size_t)(2 * l + d) * H);

    int t = threadIdx.x;

    // Front-batch the three independent weight loads (maximize MLP_p1).
    float4 w0 = wi[t];
    float4 w1 = wi[t + 256];
    float4 wh0 = wh[t];
    float4 x0 = xv[t];
    float4 x1 = xv[t + 256];
    float4 h0 = hv[t];

    float si = w0.x * x0.x + w0.y * x0.y + w0.z * x0.z + w0.w * x0.w
             + w1.x * x1.x + w1.y * x1.y + w1.z * x1.z + w1.w * x1.w;
    float sh = wh0.x * h0.x + wh0.y * h0.y + wh0.z * h0.z + wh0.w * h0.w;

    #pragma unroll
    for (int o = 16; o; o >>= 1) {
        si += __shfl_xor_sync(0xffffffffu, si, o);
        sh += __shfl_xor_sync(0xffffffffu, sh, o);
    }

    __shared__ float ri[8], rh[8];
    int warp = t >> 5, lane = t & 31;
    if (lane == 0) { ri[warp] = si; rh[warp] = sh; }
    __syncthreads();

    if (t == 0) {
        float ti = 0.f, th = 0.f;
        #pragma unroll
        for (int w = 0; w < 8; w++) { ti += ri[w]; th += rh[w]; }
        size_t boff = (size_t)(l * 2 + d) * G3 + j;
        g_gi[row] = ti + bih[boff];
        g_gh[row] = th + bhh[boff];
    }
}

// ---------------------------------------------------------------------------
// Combine: GRU nonlinearity.  16 blocks x 128 (one element per thread,
// spread across SMs to minimize the dependent-load latency chain).
// ---------------------------------------------------------------------------
__global__ void __launch_bounds__(128) combine_kernel(
    const float* __restrict__ hidden, float* __restrict__ out, int l) {

    int idx = blockIdx.x * 128 + threadIdx.x;    // 0 .. 2047
    int d = (idx >= H) ? 1 : 0;
    int j = idx - d * H;
    int base = d * G3;

    float ir  = g_gi[base + j],          hr = g_gh[base + j];
    float iz  = g_gi[base + H + j],      hz = g_gh[base + H + j];
    float in_ = g_gi[base + 2 * H + j],  hn = g_gh[base + 2 * H + j];

    float r = sigmoidf(ir + hr);
    float z = sigmoidf(iz + hz);
    float n = tanhf(in_ + r * hn);
    float hold = hidden[(size_t)(2 * l + d) * H + j];
    float hnew = (1.0f - z) * n + z * hold;

    g_x[idx] = hnew;                                  // next layer input
    out[OUTN + (size_t)(2 * l + d) * H + j] = hnew;   // new_hidden output
}

// ---------------------------------------------------------------------------
// FC: warp-per-row, 4 rows/block, 128 threads, x staged once per block.
// ---------------------------------------------------------------------------
__global__ void __launch_bounds__(128) fc_kernel(
    const float* __restrict__ fcw, const float* __restrict__ fcb,
    float* __restrict__ out) {

    __shared__ __align__(16) float sx[E];
    int tid = threadIdx.x;
    for (int i = tid; i < E; i += 128) sx[i] = g_x[i];
    __syncthreads();

    int warp = tid >> 5, lane = tid & 31;
    int r = blockIdx.x * 4 + warp;
    if (r >= OUTN) return;

    const float4* wr = (const float4*)(fcw + (size_t)r * E);
    const float4* xv = (const float4*)sx;

    float sum = 0.f;
    #pragma unroll
    for (int k = 0; k < 16; k++) {
        float4 w = wr[lane + k * 32];
        float4 x = xv[lane + k * 32];
        sum += w.x * x.x + w.y * x.y + w.z * x.z + w.w * x.w;
    }
    #pragma unroll
    for (int o = 16; o; o >>= 1) sum += __shfl_xor_sync(0xffffffffu, sum, o);

    if (lane == 0) out[r] = sum + fcb[r];
}

// ---------------------------------------------------------------------------
// 9 launches: [gates(l), combine(l)] x4, fc.   (6th captured launch = gates(2))
// Graph-capturable, allocation-free, no atomics/fences.
// ---------------------------------------------------------------------------
extern "C" void kernel_launch(void* const* d_in, const int* in_sizes, int n_in,
                              void* d_out, int out_size) {
    const int*   feat   = (const int*)  d_in[0];
    const float* hidden = (const float*)d_in[1];
    const float* table  = (const float*)d_in[2];
    const float* wih    = (const float*)d_in[3];
    const float* whh    = (const float*)d_in[4];
    const float* bih    = (const float*)d_in[5];
    const float* bhh    = (const float*)d_in[6];
    const float* fcw    = (const float*)d_in[7];
    const float* fcb    = (const float*)d_in[8];
    float* out = (float*)d_out;

    for (int l = 0; l < NL; l++) {
        gates_kernel<<<2 * G3, 256>>>(wih, whh, bih, bhh, hidden, table,
                                      feat, l);
        combine_kernel<<<16, 128>>>(hidden, out, l);
    }
    fc_kernel<<<(OUTN + 3) / 4, 128>>>(fcw, fcb, out);
}

// round 10
// speedup vs baseline: 1.2638x; 1.0212x over previous
#include <cuda_runtime.h>
#include <math.h>

#define NL 4
#define H  1024
#define E  2048
#define G3 3072
#define OUTN 50257

// Persistent scratch (__device__ globals; no allocation allowed).
__device__ float g_x[E];          // current layer input (E = 2H)
__device__ float g_gi[2 * G3];    // W_ih @ x + b_ih  (current layer)
__device__ float g_gh[2 * G3];    // W_hh @ h + b_hh  (current layer)

__device__ __forceinline__ float sigmoidf(float x) {
    return 1.0f / (1.0f + expf(-x));
}

// PDL: wait for upstream kernel's writes to be visible (full-serialization
// semantics since producers never call launch_dependents explicitly; only the
// launch ramp overlaps).  No-op when there is no programmatic predecessor.
__device__ __forceinline__ void pdl_wait() {
    asm volatile("griddepcontrol.wait;" ::: "memory");
}

// ---------------------------------------------------------------------------
// Gates: 512-thread block handles TWO consecutive rows (same layer/dir since
// G3 is even).  Per-thread pattern identical to the proven R1 shape:
// 2 float4 from W_ih + 1 float4 from W_hh, x/h straight from global (L2).
// grid = 3072.
// ---------------------------------------------------------------------------
__global__ void __launch_bounds__(512) gates_kernel(
    const float* __restrict__ wih, const float* __restrict__ whh,
    const float* __restrict__ bih, const float* __restrict__ bhh,
    const float* __restrict__ hidden, const float* __restrict__ table,
    const int* __restrict__ feat, int l) {

    pdl_wait();

    int half = threadIdx.x >> 8;     // 0 or 1: which of the 2 rows
    int t    = threadIdx.x & 255;    // thread index within the row's team

    int row = blockIdx.x * 2 + half; // 0 .. 6143
    int d = (row >= G3) ? 1 : 0;     // both rows share d (G3 even)
    int j = row - d * G3;

    const float4* wi = (const float4*)(wih + ((size_t)(l * 2 + d) * G3 + j) * E);
    const float4* wh = (const float4*)(whh + ((size_t)(l * 2 + d) * G3 + j) * H);
    const float4* xv = (l == 0)
        ? (const float4*)(table + (size_t)feat[0] * E)
        : (const float4*)g_x;
    const float4* hv = (const float4*)(hidden + (size_t)(2 * l + d) * H);

    // Front-batch the three independent weight loads.
    float4 w0  = wi[t];
    float4 w1  = wi[t + 256];
    float4 wh0 = wh[t];
    float4 x0  = xv[t];
    float4 x1  = xv[t + 256];
    float4 h0  = hv[t];

    float si = w0.x * x0.x + w0.y * x0.y + w0.z * x0.z + w0.w * x0.w
             + w1.x * x1.x + w1.y * x1.y + w1.z * x1.z + w1.w * x1.w;
    float sh = wh0.x * h0.x + wh0.y * h0.y + wh0.z * h0.z + wh0.w * h0.w;

    #pragma unroll
    for (int o = 16; o; o >>= 1) {
        si += __shfl_xor_sync(0xffffffffu, si, o);
        sh += __shfl_xor_sync(0xffffffffu, sh, o);
    }

    __shared__ float ri[16], rh[16];
    int warp = threadIdx.x >> 5, lane = threadIdx.x & 31;
    if (lane == 0) { ri[warp] = si; rh[warp] = sh; }
    __syncthreads();

    if (t == 0) {                    // threads 0 and 256: one per row
        float ti = 0.f, th = 0.f;
        #pragma unroll
        for (int w = 0; w < 8; w++) {
            ti += ri[half * 8 + w];
            th += rh[half * 8 + w];
        }
        size_t boff = (size_t)(l * 2 + d) * G3 + j;
        g_gi[row] = ti + bih[boff];
        g_gh[row] = th + bhh[boff];
    }
}

// ---------------------------------------------------------------------------
// Combine: GRU nonlinearity.  16 blocks x 128.
// ---------------------------------------------------------------------------
__global__ void __launch_bounds__(128) combine_kernel(
    const float* __restrict__ hidden, float* __restrict__ out, int l) {

    pdl_wait();

    int idx = blockIdx.x * 128 + threadIdx.x;    // 0 .. 2047
    int d = (idx >= H) ? 1 : 0;
    int j = idx - d * H;
    int base = d * G3;

    float ir  = g_gi[base + j],          hr = g_gh[base + j];
    float iz  = g_gi[base + H + j],      hz = g_gh[base + H + j];
    float in_ = g_gi[base + 2 * H + j],  hn = g_gh[base + 2 * H + j];

    float r = sigmoidf(ir + hr);
    float z = sigmoidf(iz + hz);
    float n = tanhf(in_ + r * hn);
    float hold = hidden[(size_t)(2 * l + d) * H + j];
    float hnew = (1.0f - z) * n + z * hold;

    g_x[idx] = hnew;                                  // next layer input
    out[OUTN + (size_t)(2 * l + d) * H + j] = hnew;   // new_hidden output
}

// ---------------------------------------------------------------------------
// FC: warp-per-row, 4 rows/block, 128 threads, x staged once per block.
// ---------------------------------------------------------------------------
__global__ void __launch_bounds__(128) fc_kernel(
    const float* __restrict__ fcw, const float* __restrict__ fcb,
    float* __restrict__ out) {

    pdl_wait();

    __shared__ __align__(16) float sx[E];
    int tid = threadIdx.x;
    for (int i = tid; i < E; i += 128) sx[i] = g_x[i];
    __syncthreads();

    int warp = tid >> 5, lane = tid & 31;
    int r = blockIdx.x * 4 + warp;
    if (r >= OUTN) return;

    const float4* wr = (const float4*)(fcw + (size_t)r * E);
    const float4* xv = (const float4*)sx;

    float sum = 0.f;
    #pragma unroll
    for (int k = 0; k < 16; k++) {
        float4 w = wr[lane + k * 32];
        float4 x = xv[lane + k * 32];
        sum += w.x * x.x + w.y * x.y + w.z * x.z + w.w * x.w;
    }
    #pragma unroll
    for (int o = 16; o; o >>= 1) sum += __shfl_xor_sync(0xffffffffu, sum, o);

    if (lane == 0) out[r] = sum + fcb[r];
}

// ---------------------------------------------------------------------------
// 9 launches: [gates(l), combine(l)] x4, fc — all with the PDL
// ProgrammaticStreamSerialization attribute so launch ramps overlap the
// predecessor's tail.  Graph-capturable (PDL edges are capture-supported),
// allocation-free, no atomics/fences.
// ---------------------------------------------------------------------------
template <typename... Args>
static void launch_pdl(void (*kern)(Args...), dim3 grid, dim3 block,
                       Args... args) {
    cudaLaunchConfig_t cfg = {};
    cfg.gridDim = grid;
    cfg.blockDim = block;
    cudaLaunchAttribute attr[1];
    attr[0].id = cudaLaunchAttributeProgrammaticStreamSerialization;
    attr[0].val.programmaticStreamSerializationAllowed = 1;
    cfg.attrs = attr;
    cfg.numAttrs = 1;
    cudaLaunchKernelEx(&cfg, kern, args...);
}

extern "C" void kernel_launch(void* const* d_in, const int* in_sizes, int n_in,
                              void* d_out, int out_size) {
    const int*   feat   = (const int*)  d_in[0];
    const float* hidden = (const float*)d_in[1];
    const float* table  = (const float*)d_in[2];
    const float* wih    = (const float*)d_in[3];
    const float* whh    = (const float*)d_in[4];
    const float* bih    = (const float*)d_in[5];
    const float* bhh    = (const float*)d_in[6];
    const float* fcw    = (const float*)d_in[7];
    const float* fcb    = (const float*)d_in[8];
    float* out = (float*)d_out;

    for (int l = 0; l < NL; l++) {
        launch_pdl(gates_kernel, dim3(G3), dim3(512),
                   wih, whh, bih, bhh, hidden, table, feat, l);
        launch_pdl(combine_kernel, dim3(16), dim3(128), hidden, out, l);
    }
    launch_pdl(fc_kernel, dim3((OUTN + 3) / 4), dim3(128), fcw, fcb, out);
}